// round 2
// baseline (speedup 1.0000x reference)
#include <cuda_runtime.h>
#include <cstdint>

// Hash-grid 2D bilinear encoding (lane-paired gather).
// x: [N,2] f32 in [-1,1); table: [2^22, 8] f32; out: [N,8] f32.
// hash = (ix*73856093 ^ iy*19349663) mod 2^22  (low 22 bits -> 32-bit mul exact)
//
// Two consecutive threads cooperate on one point: lane parity selects which
// 16B half of each 32B table entry to load, so the pair's two LDG.128 for a
// corner land in the same 128B line IN THE SAME INSTRUCTION -> 1 L1tex
// wavefront per corner instead of 2.

#define BLOCK 256
static constexpr unsigned P0 = 73856093u;
static constexpr unsigned P1 = 19349663u;
static constexpr unsigned HMASK = (1u << 22) - 1u;

__global__ __launch_bounds__(BLOCK) void hashgrid_kernel(
    const float2* __restrict__ x,
    const float4* __restrict__ table4,   // 2 float4 per entry
    float4* __restrict__ out4,           // 2 float4 per point
    int n)                               // number of points
{
    int t = blockIdx.x * BLOCK + threadIdx.x;
    int i    = t >> 1;        // point index
    int half = t & 1;         // which float4 of the 8-feature entry
    if (i >= n) return;

    float2 p = x[i];
    // (x+1)*0.5*1024 == (x+1)*512 exactly (power-of-two scale)
    float xs = (p.x + 1.0f) * 512.0f;
    float ys = (p.y + 1.0f) * 512.0f;
    int ix = (int)xs;         // xs >= 0 -> trunc == floor
    int iy = (int)ys;
    float fx = xs - (float)ix;
    float fy = ys - (float)iy;

    unsigned a0 = (unsigned)ix * P0;
    unsigned a1 = a0 + P0;    // (ix+1)*P0 mod 2^32
    unsigned b0 = (unsigned)iy * P1;
    unsigned b1 = b0 + P1;

    unsigned h00 = (a0 ^ b0) & HMASK;
    unsigned h10 = (a1 ^ b0) & HMASK;
    unsigned h01 = (a0 ^ b1) & HMASK;
    unsigned h11 = (a1 ^ b1) & HMASK;

    float gx = 1.0f - fx;
    float gy = 1.0f - fy;
    float w00 = gx * gy;
    float w10 = fx * gy;
    float w01 = gx * fy;
    float w11 = fx * fy;

    // Each lane of the pair loads its half of each corner entry.
    // Even lane: offset 0; odd lane: offset 1 (16B). Same 128B line as partner.
    float4 v00 = table4[2u * (size_t)h00 + (unsigned)half];
    float4 v10 = table4[2u * (size_t)h10 + (unsigned)half];
    float4 v01 = table4[2u * (size_t)h01 + (unsigned)half];
    float4 v11 = table4[2u * (size_t)h11 + (unsigned)half];

    float4 s;
    s.x = w00 * v00.x; s.y = w00 * v00.y; s.z = w00 * v00.z; s.w = w00 * v00.w;
    s.x += w10 * v10.x; s.y += w10 * v10.y; s.z += w10 * v10.z; s.w += w10 * v10.w;
    s.x += w01 * v01.x; s.y += w01 * v01.y; s.z += w01 * v01.z; s.w += w01 * v01.w;
    s.x += w11 * v11.x; s.y += w11 * v11.y; s.z += w11 * v11.z; s.w += w11 * v11.w;

    out4[2 * (size_t)i + (unsigned)half] = s;
}

extern "C" void kernel_launch(void* const* d_in, const int* in_sizes, int n_in,
                              void* d_out, int out_size)
{
    const float2* x      = (const float2*)d_in[0];
    const float4* table4 = (const float4*)d_in[1];
    float4* out4         = (float4*)d_out;
    int n = in_sizes[0] / 2;            // [N,2] f32 -> N points
    long long threads = 2LL * n;        // 2 threads per point
    int grid = (int)((threads + BLOCK - 1) / BLOCK);
    hashgrid_kernel<<<grid, BLOCK>>>(x, table4, out4, n);
}

// round 4
// speedup vs baseline: 1.0638x; 1.0638x over previous
#include <cuda_runtime.h>
#include <cstdint>

// Hash-grid 2D bilinear encoding (lane-paired gather + L2 policy control).
// x: [N,2] f32 in [-1,1); table: [2^22, 8] f32; out: [N,8] f32.
// hash = (ix*73856093 ^ iy*19349663) mod 2^22 (low 22 bits -> 32-bit mul exact)
//
// vs 102.4us baseline:
//  - out stores via __stcs (L2 evict-first): 128 MB of streaming writes no
//    longer evict table lines from L2.
//  - x loads via __ldcs (read-once streaming).
//  - table gathers via ld.global.nc with createpolicy L2::evict_last, pinning
//    the ~134 MB table working set as preferred L2 residents.

#define BLOCK 256
static constexpr unsigned P0 = 73856093u;
static constexpr unsigned P1 = 19349663u;
static constexpr unsigned HMASK = (1u << 22) - 1u;

__device__ __forceinline__ uint64_t mk_evict_last_policy() {
    uint64_t pol;
    asm("createpolicy.fractional.L2::evict_last.b64 %0, 1.0;" : "=l"(pol));
    return pol;
}

__device__ __forceinline__ float4 ldg_nc_el(const float4* p, uint64_t pol) {
    float4 v;
    asm("ld.global.nc.L2::cache_hint.v4.f32 {%0,%1,%2,%3}, [%4], %5;"
        : "=f"(v.x), "=f"(v.y), "=f"(v.z), "=f"(v.w)
        : "l"(p), "l"(pol));
    return v;
}

__global__ __launch_bounds__(BLOCK) void hashgrid_kernel(
    const float2* __restrict__ x,
    const float4* __restrict__ table4,   // 2 float4 per entry
    float4* __restrict__ out4,           // 2 float4 per point
    int n)                               // number of points
{
    int t = blockIdx.x * BLOCK + threadIdx.x;
    int i    = t >> 1;        // point index
    int half = t & 1;         // which float4 of the 8-feature entry
    if (i >= n) return;

    const uint64_t pol = mk_evict_last_policy();

    float2 p = __ldcs(&x[i]);
    // (x+1)*0.5*1024 == (x+1)*512 exactly (power-of-two scale)
    float xs = (p.x + 1.0f) * 512.0f;
    float ys = (p.y + 1.0f) * 512.0f;
    int ix = (int)xs;         // xs >= 0 -> trunc == floor
    int iy = (int)ys;
    float fx = xs - (float)ix;
    float fy = ys - (float)iy;

    unsigned a0 = (unsigned)ix * P0;
    unsigned a1 = a0 + P0;    // (ix+1)*P0 mod 2^32
    unsigned b0 = (unsigned)iy * P1;
    unsigned b1 = b0 + P1;

    unsigned h00 = (a0 ^ b0) & HMASK;
    unsigned h10 = (a1 ^ b0) & HMASK;
    unsigned h01 = (a0 ^ b1) & HMASK;
    unsigned h11 = (a1 ^ b1) & HMASK;

    float gx = 1.0f - fx;
    float gy = 1.0f - fy;
    float w00 = gx * gy;
    float w10 = fx * gy;
    float w01 = gx * fy;
    float w11 = fx * fy;

    // Each lane of the pair loads its 16B half of each 32B corner entry:
    // pair's two addresses share a 128B line within the same instruction.
    float4 v00 = ldg_nc_el(table4 + 2u * (size_t)h00 + (unsigned)half, pol);
    float4 v10 = ldg_nc_el(table4 + 2u * (size_t)h10 + (unsigned)half, pol);
    float4 v01 = ldg_nc_el(table4 + 2u * (size_t)h01 + (unsigned)half, pol);
    float4 v11 = ldg_nc_el(table4 + 2u * (size_t)h11 + (unsigned)half, pol);

    float4 s;
    s.x = w00 * v00.x; s.y = w00 * v00.y; s.z = w00 * v00.z; s.w = w00 * v00.w;
    s.x += w10 * v10.x; s.y += w10 * v10.y; s.z += w10 * v10.z; s.w += w10 * v10.w;
    s.x += w01 * v01.x; s.y += w01 * v01.y; s.z += w01 * v01.z; s.w += w01 * v01.w;
    s.x += w11 * v11.x; s.y += w11 * v11.y; s.z += w11 * v11.z; s.w += w11 * v11.w;

    __stcs(&out4[2 * (size_t)i + (unsigned)half], s);
}

extern "C" void kernel_launch(void* const* d_in, const int* in_sizes, int n_in,
                              void* d_out, int out_size)
{
    const float2* x      = (const float2*)d_in[0];
    const float4* table4 = (const float4*)d_in[1];
    float4* out4         = (float4*)d_out;
    int n = in_sizes[0] / 2;            // [N,2] f32 -> N points
    long long threads = 2LL * n;        // 2 threads per point
    int grid = (int)((threads + BLOCK - 1) / BLOCK);
    hashgrid_kernel<<<grid, BLOCK>>>(x, table4, out4, n);
}